// round 1
// baseline (speedup 1.0000x reference)
#include <cuda_runtime.h>
#include <cuda_bf16.h>
#include <cstdint>

// ---------------------------------------------------------------------------
// GlobalMatchingTokenizer: 3 levels of efficient global matching attention.
// Level l: B=2, C={64,128,192}, H=W={64,32,16}, N=H*W, TOKEN_DIM=192,
// NUM_HEADS=4, HEAD_DIM=48, TOPK=128.
// Pipeline per level:
//   1) proj:   Q=f1@qw+qb+pe, K=f2@kw+kb+pe, V=f2@vw+vb   (split to heads)
//   2) scores: S[b,h,n,m] = (Q.K)/sqrt(48)   (materialized in scratch)
//   3) attn:   exact top-128 per row (radix select), softmax, AV gather
//   4) oproj:  out = concat_heads @ ow + ob  -> [B,192,H,W]
// ---------------------------------------------------------------------------

#define NH 4
#define HD 48
#define TD 192
#define KSEL 128

// Scratch (device globals: allowed; no dynamic allocation anywhere).
__device__ float g_S[134217728];            // 2*4*4096*4096 floats = 512 MB
__device__ float g_Q[2 * NH * 4096 * HD];   // 6 MB each
__device__ float g_K[2 * NH * 4096 * HD];
__device__ float g_V[2 * NH * 4096 * HD];
__device__ float g_O[2 * NH * 4096 * HD];

// ---------------------------------------------------------------------------
// Kernel 1: QKV projection + positional encoding.
// grid = B*N blocks, 192 threads. Shared: feature rows of f1, f2.
// ---------------------------------------------------------------------------
__global__ void proj_kernel(const float* __restrict__ f1,
                            const float* __restrict__ f2,
                            const float* __restrict__ qw, const float* __restrict__ qb,
                            const float* __restrict__ kw, const float* __restrict__ kb,
                            const float* __restrict__ vw, const float* __restrict__ vb,
                            int C, int N, int W)
{
    __shared__ float s1[192];
    __shared__ float s2[192];
    const int t = threadIdx.x;               // 0..191 (output channel)
    const int n = blockIdx.x % N;
    const int b = blockIdx.x / N;

    for (int c = t; c < C; c += 192) {
        s1[c] = f1[((size_t)b * C + c) * N + n];
        s2[c] = f2[((size_t)b * C + c) * N + n];
    }
    __syncthreads();

    float q = qb[t], k = kb[t], v = vb[t];
    for (int c = 0; c < C; ++c) {
        const float a1 = s1[c];
        const float a2 = s2[c];
        q = fmaf(a1, qw[c * TD + t], q);
        k = fmaf(a2, kw[c * TD + t], k);
        v = fmaf(a2, vw[c * TD + t], v);
    }

    // 2D sinusoidal positional encoding (dh = 96 for both halves).
    const float step = -9.210340371976184f / 96.0f;  // -ln(10000)/96
    float pe;
    if (t < 96) {
        const float x = (float)(n % W);
        pe = sinf(x * expf(step * (float)t));
    } else {
        const float y = (float)(n / W);
        pe = cosf(y * expf(step * (float)(t - 96)));
    }
    q += pe;
    k += pe;

    const int h = t / HD;
    const int d = t % HD;
    const size_t idx = ((((size_t)b * NH + h) * N) + n) * HD + d;
    g_Q[idx] = q;
    g_K[idx] = k;
    g_V[idx] = v;
}

// ---------------------------------------------------------------------------
// Kernel 2: scores GEMM. S[bh][n][m] = scale * dot(Q[bh][n], K[bh][m]).
// grid = (N/64, N/64, B*NH), block = 16x16, 4x4 outputs per thread.
// ---------------------------------------------------------------------------
__global__ void scores_kernel(int N)
{
    __shared__ float Qs[64][49];
    __shared__ float Ks[64][49];

    const int bh = blockIdx.z;
    const float* __restrict__ Qb = g_Q + (size_t)bh * N * HD;
    const float* __restrict__ Kb = g_K + (size_t)bh * N * HD;
    float* __restrict__ Sb = g_S + (size_t)bh * N * N;

    const int tid = threadIdx.y * 16 + threadIdx.x;
    const int rb = blockIdx.y * 64;
    const int cb = blockIdx.x * 64;

    for (int i = tid; i < 64 * HD; i += 256) {
        const int r = i / HD, kk = i % HD;
        Qs[r][kk] = Qb[(size_t)(rb + r) * HD + kk];
        Ks[r][kk] = Kb[(size_t)(cb + r) * HD + kk];
    }
    __syncthreads();

    float acc[4][4] = {};
    const int ty = threadIdx.y, tx = threadIdx.x;
    #pragma unroll 8
    for (int kk = 0; kk < HD; ++kk) {
        float qv[4], kv[4];
        #pragma unroll
        for (int i = 0; i < 4; ++i) { qv[i] = Qs[ty * 4 + i][kk]; kv[i] = Ks[tx * 4 + i][kk]; }
        #pragma unroll
        for (int i = 0; i < 4; ++i)
            #pragma unroll
            for (int j = 0; j < 4; ++j)
                acc[i][j] = fmaf(qv[i], kv[j], acc[i][j]);
    }

    const float scale = 0.14433756729740643f;  // 1/sqrt(48)
    #pragma unroll
    for (int i = 0; i < 4; ++i) {
        const size_t rowoff = (size_t)(rb + ty * 4 + i) * N + cb + tx * 4;
        #pragma unroll
        for (int j = 0; j < 4; ++j)
            Sb[rowoff + j] = acc[i][j] * scale;
    }
}

// ---------------------------------------------------------------------------
// Kernel 3: per query row: exact top-128 (radix select on sortable keys),
// softmax over selected values, weighted V sum. grid = B*NH*N rows, 256 thr.
// ---------------------------------------------------------------------------
__device__ __forceinline__ unsigned int floatToKey(float f)
{
    unsigned int u = __float_as_uint(f);
    return (u & 0x80000000u) ? ~u : (u | 0x80000000u);
}
__device__ __forceinline__ float keyToFloat(unsigned int u)
{
    unsigned int b = (u & 0x80000000u) ? (u & 0x7fffffffu) : ~u;
    return __uint_as_float(b);
}

__global__ void attn_kernel(int N)
{
    extern __shared__ unsigned int keys[];      // N sortable keys
    __shared__ unsigned int hist[256];
    __shared__ float        wl[KSEL];
    __shared__ int          ml[KSEL];
    __shared__ float        accs[HD];
    __shared__ unsigned int s_prefix, s_maxkey;
    __shared__ int          s_need, s_cnt;
    __shared__ float        s_Z;

    const int tid = threadIdx.x;                // 0..255
    const size_t row = blockIdx.x;              // (b*NH+h)*N + n
    const float* __restrict__ Srow = g_S + row * (size_t)N;

    if (tid == 0) { s_maxkey = 0u; s_cnt = 0; s_Z = 0.f; s_prefix = 0u; s_need = KSEL; }
    if (tid < HD) accs[tid] = 0.f;
    __syncthreads();

    unsigned int lmax = 0u;
    for (int m = tid; m < N; m += 256) {
        const unsigned int u = floatToKey(Srow[m]);
        keys[m] = u;
        lmax = max(lmax, u);
    }
    atomicMax(&s_maxkey, lmax);
    __syncthreads();

    // 4-pass radix select for the 128th-largest key.
    for (int pass = 0; pass < 4; ++pass) {
        hist[tid & 255] = 0u;  // blockDim=256 covers all bins
        __syncthreads();
        const int shift = 24 - 8 * pass;
        const unsigned int pfx = s_prefix;
        for (int m = tid; m < N; m += 256) {
            const unsigned int u = keys[m];
            if (pass == 0 || (u >> (shift + 8)) == pfx)
                atomicAdd(&hist[(u >> shift) & 255u], 1u);
        }
        __syncthreads();
        if (tid == 0) {
            const int need = s_need;
            int cum = 0, bsel = 0;
            for (int b = 255; b >= 0; --b) {
                cum += (int)hist[b];
                if (cum >= need) { bsel = b; break; }
            }
            s_need   = need - (cum - (int)hist[bsel]);
            s_prefix = (pfx << 8) | (unsigned int)bsel;
        }
        __syncthreads();
    }

    const unsigned int T = s_prefix;
    const int nTie = s_need;
    const float smax = keyToFloat(s_maxkey);

    // Take-pass: all keys > T, plus the nTie lowest-index keys == T.
    for (int m = tid; m < N; m += 256) {
        const unsigned int u = keys[m];
        bool take = (u > T);
        if (u == T) {
            int r = 0;
            for (int j = 0; j < m; ++j) r += (keys[j] == T);
            take = (r < nTie);
        }
        if (take) {
            const int slot = atomicAdd(&s_cnt, 1);
            if (slot < KSEL) {
                const float w = __expf(keyToFloat(u) - smax);
                wl[slot] = w;
                ml[slot] = m;
                atomicAdd(&s_Z, w);
            }
        }
    }
    __syncthreads();

    const int total = min(s_cnt, KSEL);
    const size_t bh = row / (size_t)N;
    const float* __restrict__ Vb = g_V + bh * (size_t)N * HD;

    if (tid < 192) {
        const int d = tid % HD;
        const int ch = tid / HD;   // 4 chunks
        float a = 0.f;
        for (int i = ch; i < total; i += 4)
            a = fmaf(wl[i], Vb[(size_t)ml[i] * HD + d], a);
        atomicAdd(&accs[d], a);
    }
    __syncthreads();

    if (tid < HD)
        g_O[row * HD + tid] = accs[tid] / s_Z;
}

// ---------------------------------------------------------------------------
// Kernel 4: output projection. out[b,t,n] = sum_j O[b,n,j]*ow[j,t] + ob[t].
// grid = B*N, 192 threads.
// ---------------------------------------------------------------------------
__global__ void oproj_kernel(const float* __restrict__ ow,
                             const float* __restrict__ ob,
                             float* __restrict__ out, int N)
{
    __shared__ float o[TD];
    const int t = threadIdx.x;
    const int n = blockIdx.x % N;
    const int b = blockIdx.x / N;

    o[t] = g_O[(((size_t)b * NH + t / HD) * N + n) * HD + (t % HD)];
    __syncthreads();

    float acc = ob[t];
    #pragma unroll 8
    for (int j = 0; j < TD; ++j)
        acc = fmaf(o[j], ow[j * TD + t], acc);

    out[((size_t)b * TD + t) * N + n] = acc;
}

// ---------------------------------------------------------------------------
// Launch: 3 levels sequentially. Input order follows reference signature:
// feat1_0, feat2_0, feat1_1, feat2_1, feat1_2, feat2_2,
// then per-level: qw, qb, kw, kb, vw, vb, ow, ob.
// ---------------------------------------------------------------------------
extern "C" void kernel_launch(void* const* d_in, const int* in_sizes, int n_in,
                              void* d_out, int out_size)
{
    (void)in_sizes; (void)n_in; (void)out_size;

    const int Cs[3] = {64, 128, 192};
    const int Hs[3] = {64, 32, 16};

    size_t out_off = 0;
    for (int l = 0; l < 3; ++l) {
        const int C = Cs[l];
        const int H = Hs[l];
        const int N = H * H;
        const int B = 2;

        const float* f1 = (const float*)d_in[2 * l + 0];
        const float* f2 = (const float*)d_in[2 * l + 1];
        const int wb = 6 + 8 * l;
        const float* qw = (const float*)d_in[wb + 0];
        const float* qb = (const float*)d_in[wb + 1];
        const float* kw = (const float*)d_in[wb + 2];
        const float* kb = (const float*)d_in[wb + 3];
        const float* vw = (const float*)d_in[wb + 4];
        const float* vb = (const float*)d_in[wb + 5];
        const float* ow = (const float*)d_in[wb + 6];
        const float* ob = (const float*)d_in[wb + 7];

        float* outp = (float*)d_out + out_off;

        proj_kernel<<<B * N, 192>>>(f1, f2, qw, qb, kw, kb, vw, vb, C, N, H);

        dim3 sg(N / 64, N / 64, B * NH);
        scores_kernel<<<sg, dim3(16, 16)>>>(N);

        attn_kernel<<<B * NH * N, 256, (size_t)N * sizeof(unsigned int)>>>(N);

        oproj_kernel<<<B * N, 192>>>(ow, ob, outp, N);

        out_off += (size_t)B * TD * N;
    }
}

// round 2
// speedup vs baseline: 1.3810x; 1.3810x over previous
#include <cuda_runtime.h>
#include <cuda_bf16.h>
#include <cstdint>

// ---------------------------------------------------------------------------
// GlobalMatchingTokenizer: 3 levels of efficient global matching attention.
// Level l: B=2, C={64,128,192}, H=W={64,32,16}, N=H*W, TOKEN_DIM=192,
// NUM_HEADS=4, HEAD_DIM=48, TOPK=128.
// ---------------------------------------------------------------------------

#define NH 4
#define HD 48
#define TD 192
#define KSEL 128
#define TN 16      // query-position tile for proj/oproj
#define CAP 256    // candidate cap for single-pass radix select

// Scratch (device globals: allowed; no dynamic allocation anywhere).
__device__ float g_S[134217728];            // 2*4*4096*4096 floats = 512 MB
__device__ float g_Q[2 * NH * 4096 * HD];
__device__ float g_K[2 * NH * 4096 * HD];
__device__ float g_V[2 * NH * 4096 * HD];
__device__ float g_O[2 * NH * 4096 * HD];

// ---------------------------------------------------------------------------
// Kernel 1: QKV projection + positional encoding, n-tiled for weight reuse.
// grid = B*(N/TN), 192 threads (one per output channel), TN positions/block.
// ---------------------------------------------------------------------------
__global__ void proj_kernel(const float* __restrict__ f1,
                            const float* __restrict__ f2,
                            const float* __restrict__ qw, const float* __restrict__ qb,
                            const float* __restrict__ kw, const float* __restrict__ kb,
                            const float* __restrict__ vw, const float* __restrict__ vb,
                            int C, int N, int W)
{
    __shared__ float s1[TD][TN];
    __shared__ float s2[TD][TN];
    const int t  = threadIdx.x;                 // output channel 0..191
    const int nt = N / TN;
    const int n0 = (blockIdx.x % nt) * TN;
    const int b  = blockIdx.x / nt;

    for (int i = t; i < C * TN; i += 192) {
        const int c = i / TN, j = i % TN;
        s1[c][j] = f1[((size_t)b * C + c) * N + n0 + j];
        s2[c][j] = f2[((size_t)b * C + c) * N + n0 + j];
    }
    __syncthreads();

    float aq[TN], ak[TN], av[TN];
    const float bq = qb[t], bk = kb[t], bv = vb[t];
    #pragma unroll
    for (int j = 0; j < TN; ++j) { aq[j] = bq; ak[j] = bk; av[j] = bv; }

    for (int c = 0; c < C; ++c) {
        const float wq = qw[c * TD + t];
        const float wk = kw[c * TD + t];
        const float wv = vw[c * TD + t];
        #pragma unroll
        for (int j = 0; j < TN; ++j) {
            const float a1 = s1[c][j];
            const float a2 = s2[c][j];
            aq[j] = fmaf(a1, wq, aq[j]);
            ak[j] = fmaf(a2, wk, ak[j]);
            av[j] = fmaf(a2, wv, av[j]);
        }
    }

    // 2D sinusoidal positional encoding.
    const float step = -9.210340371976184f / 96.0f;  // -ln(10000)/96
    const float div  = expf(step * (float)(t < 96 ? t : t - 96));
    #pragma unroll
    for (int j = 0; j < TN; ++j) {
        const int n = n0 + j;
        const float pe = (t < 96) ? sinf((float)(n % W) * div)
                                  : cosf((float)(n / W) * div);
        aq[j] += pe;
        ak[j] += pe;
    }

    const int h = t / HD;
    const int d = t % HD;
    const size_t base = (((size_t)b * NH + h) * N + n0) * HD + d;
    #pragma unroll
    for (int j = 0; j < TN; ++j) {
        g_Q[base + (size_t)j * HD] = aq[j];
        g_K[base + (size_t)j * HD] = ak[j];
        g_V[base + (size_t)j * HD] = av[j];
    }
}

// ---------------------------------------------------------------------------
// Kernel 2: scores GEMM. S[bh][n][m] = scale * dot(Q[bh][n], K[bh][m]).
// grid = (N/64, N/64, B*NH), block = 16x16, 4x4 outputs per thread.
// ---------------------------------------------------------------------------
__global__ void scores_kernel(int N)
{
    __shared__ float Qs[64][49];
    __shared__ float Ks[64][49];

    const int bh = blockIdx.z;
    const float* __restrict__ Qb = g_Q + (size_t)bh * N * HD;
    const float* __restrict__ Kb = g_K + (size_t)bh * N * HD;
    float* __restrict__ Sb = g_S + (size_t)bh * N * N;

    const int tid = threadIdx.y * 16 + threadIdx.x;
    const int rb = blockIdx.y * 64;
    const int cb = blockIdx.x * 64;

    for (int i = tid; i < 64 * HD; i += 256) {
        const int r = i / HD, kk = i % HD;
        Qs[r][kk] = Qb[(size_t)(rb + r) * HD + kk];
        Ks[r][kk] = Kb[(size_t)(cb + r) * HD + kk];
    }
    __syncthreads();

    float acc[4][4] = {};
    const int ty = threadIdx.y, tx = threadIdx.x;
    #pragma unroll 8
    for (int kk = 0; kk < HD; ++kk) {
        float qv[4], kv[4];
        #pragma unroll
        for (int i = 0; i < 4; ++i) { qv[i] = Qs[ty * 4 + i][kk]; kv[i] = Ks[tx * 4 + i][kk]; }
        #pragma unroll
        for (int i = 0; i < 4; ++i)
            #pragma unroll
            for (int j = 0; j < 4; ++j)
                acc[i][j] = fmaf(qv[i], kv[j], acc[i][j]);
    }

    const float scale = 0.14433756729740643f;  // 1/sqrt(48)
    #pragma unroll
    for (int i = 0; i < 4; ++i) {
        const size_t rowoff = (size_t)(rb + ty * 4 + i) * N + cb + tx * 4;
        #pragma unroll
        for (int j = 0; j < 4; ++j)
            Sb[rowoff + j] = acc[i][j] * scale;
    }
}

// ---------------------------------------------------------------------------
// Kernel 3: per query row: exact top-128 via single-pass radix + candidate
// refinement, softmax, weighted V sum. grid = B*NH*N rows, 256 threads.
// ---------------------------------------------------------------------------
__device__ __forceinline__ unsigned int floatToKey(float f)
{
    unsigned int u = __float_as_uint(f);
    return (u & 0x80000000u) ? ~u : (u | 0x80000000u);
}
__device__ __forceinline__ float keyToFloat(unsigned int u)
{
    unsigned int b = (u & 0x80000000u) ? (u & 0x7fffffffu) : ~u;
    return __uint_as_float(b);
}

__global__ void attn_kernel(int N)
{
    extern __shared__ unsigned int keys[];      // N sortable keys
    __shared__ unsigned int hist[256];
    __shared__ unsigned int ckey[CAP];
    __shared__ int          cidx[CAP];
    __shared__ float        wl[KSEL];
    __shared__ int          ml[KSEL];
    __shared__ float        accs[HD];
    __shared__ unsigned int s_prefix, s_maxkey;
    __shared__ int          s_need, s_cand, s_cnt, s_ccnt;
    __shared__ float        s_Z;

    const int tid = threadIdx.x;                // 0..255
    const size_t row = blockIdx.x;              // (b*NH+h)*N + n
    const float* __restrict__ Srow = g_S + row * (size_t)N;

    if (tid == 0) {
        s_maxkey = 0u; s_cnt = 0; s_ccnt = 0; s_Z = 0.f;
        s_prefix = 0u; s_need = KSEL;
    }
    if (tid < HD) accs[tid] = 0.f;
    hist[tid] = 0u;
    __syncthreads();

    // Fused load + key conversion + pass-0 histogram (top 8 bits).
    unsigned int lmax = 0u;
    for (int m = tid; m < N; m += 256) {
        const unsigned int u = floatToKey(Srow[m]);
        keys[m] = u;
        lmax = max(lmax, u);
        atomicAdd(&hist[u >> 24], 1u);
    }
    atomicMax(&s_maxkey, lmax);
    __syncthreads();

    // Radix select loop: usually terminates after pass 0 with <= CAP candidates.
    int p = 0;
    for (;;) {
        const int shift = 24 - 8 * p;
        if (tid == 0) {
            const int need = s_need;
            int cum = 0;
            for (int b = 255; b >= 0; --b) {
                cum += (int)hist[b];
                if (cum >= need) {
                    s_need   = need - (cum - (int)hist[b]);
                    s_cand   = (int)hist[b];
                    s_prefix = (s_prefix << 8) | (unsigned int)b;
                    break;
                }
            }
        }
        __syncthreads();
        if (s_cand <= CAP || p == 3) break;

        // Build histogram of next 8 bits among current candidates.
        hist[tid] = 0u;
        __syncthreads();
        const unsigned int pfx = s_prefix;
        const int nshift = shift - 8;
        for (int m = tid; m < N; m += 256) {
            const unsigned int u = keys[m];
            if ((u >> shift) == pfx)
                atomicAdd(&hist[(u >> nshift) & 255u], 1u);
        }
        __syncthreads();
        ++p;
    }

    const int shift = 24 - 8 * p;
    const unsigned int P = s_prefix;
    const int needC = s_need;
    const int cand  = s_cand;
    const float smax = keyToFloat(s_maxkey);

    // Definite winners: keys strictly above the selected bucket.
    for (int m = tid; m < N; m += 256) {
        const unsigned int u = keys[m];
        if ((u >> shift) > P) {
            const int slot = atomicAdd(&s_cnt, 1);
            if (slot < KSEL) {
                const float w = __expf(keyToFloat(u) - smax);
                wl[slot] = w; ml[slot] = m;
                atomicAdd(&s_Z, w);
            }
        }
    }

    if (cand <= CAP) {
        // Gather bucket candidates, then exact rank (key desc, index asc).
        for (int m = tid; m < N; m += 256) {
            const unsigned int u = keys[m];
            if ((u >> shift) == P) {
                const int slot = atomicAdd(&s_ccnt, 1);
                if (slot < CAP) { ckey[slot] = u; cidx[slot] = m; }
            }
        }
        __syncthreads();
        const int c = min(s_ccnt, CAP);
        for (int i = tid; i < c; i += 256) {
            const unsigned int ki = ckey[i];
            const int idi = cidx[i];
            int r = 0;
            for (int j = 0; j < c; ++j) {
                const unsigned int kj = ckey[j];
                r += (kj > ki) || (kj == ki && cidx[j] < idi);
            }
            if (r < needC) {
                const int slot = atomicAdd(&s_cnt, 1);
                if (slot < KSEL) {
                    const float w = __expf(keyToFloat(ki) - smax);
                    wl[slot] = w; ml[slot] = idi;
                    atomicAdd(&s_Z, w);
                }
            }
        }
    } else {
        // Pathological: >CAP keys identical on all 32 bits (shift == 0).
        // Tie-break by index with an O(m) scan (exactness fallback).
        for (int m = tid; m < N; m += 256) {
            const unsigned int u = keys[m];
            if (u == P) {
                int r = 0;
                for (int j = 0; j < m; ++j) r += (keys[j] == P);
                if (r < needC) {
                    const int slot = atomicAdd(&s_cnt, 1);
                    if (slot < KSEL) {
                        const float w = __expf(keyToFloat(u) - smax);
                        wl[slot] = w; ml[slot] = m;
                        atomicAdd(&s_Z, w);
                    }
                }
            }
        }
    }
    __syncthreads();

    const int total = min(s_cnt, KSEL);
    const size_t bh = row / (size_t)N;
    const float* __restrict__ Vb = g_V + bh * (size_t)N * HD;

    if (tid < 192) {
        const int d = tid % HD;
        const int ch = tid / HD;   // 4 chunks
        float a = 0.f;
        for (int i = ch; i < total; i += 4)
            a = fmaf(wl[i], Vb[(size_t)ml[i] * HD + d], a);
        atomicAdd(&accs[d], a);
    }
    __syncthreads();

    if (tid < HD)
        g_O[row * HD + tid] = accs[tid] / s_Z;
}

// ---------------------------------------------------------------------------
// Kernel 4: output projection, n-tiled for ow reuse.
// grid = B*(N/TN), 192 threads.
// ---------------------------------------------------------------------------
__global__ void oproj_kernel(const float* __restrict__ ow,
                             const float* __restrict__ ob,
                             float* __restrict__ out, int N)
{
    __shared__ float o[TD][TN + 1];
    const int t  = threadIdx.x;
    const int nt = N / TN;
    const int n0 = (blockIdx.x % nt) * TN;
    const int b  = blockIdx.x / nt;

    for (int i = t; i < TD * TN; i += 192) {
        const int j  = i / TD;     // position within tile
        const int td = i % TD;     // token channel
        const int h = td / HD, d = td % HD;
        o[td][j] = g_O[(((size_t)b * NH + h) * N + n0 + j) * HD + d];
    }
    __syncthreads();

    float acc[TN];
    const float bias = ob[t];
    #pragma unroll
    for (int j = 0; j < TN; ++j) acc[j] = bias;

    for (int j = 0; j < TD; ++j) {
        const float w = ow[j * TD + t];
        #pragma unroll
        for (int jj = 0; jj < TN; ++jj)
            acc[jj] = fmaf(o[j][jj], w, acc[jj]);
    }

    float4* op = (float4*)(out + ((size_t)b * TD + t) * N + n0);
    #pragma unroll
    for (int q = 0; q < TN / 4; ++q)
        op[q] = make_float4(acc[4 * q], acc[4 * q + 1], acc[4 * q + 2], acc[4 * q + 3]);
}

// ---------------------------------------------------------------------------
// Launch: 3 levels sequentially.
// ---------------------------------------------------------------------------
extern "C" void kernel_launch(void* const* d_in, const int* in_sizes, int n_in,
                              void* d_out, int out_size)
{
    (void)in_sizes; (void)n_in; (void)out_size;

    const int Cs[3] = {64, 128, 192};
    const int Hs[3] = {64, 32, 16};

    size_t out_off = 0;
    for (int l = 0; l < 3; ++l) {
        const int C = Cs[l];
        const int H = Hs[l];
        const int N = H * H;
        const int B = 2;

        const float* f1 = (const float*)d_in[2 * l + 0];
        const float* f2 = (const float*)d_in[2 * l + 1];
        const int wb = 6 + 8 * l;
        const float* qw = (const float*)d_in[wb + 0];
        const float* qb = (const float*)d_in[wb + 1];
        const float* kw = (const float*)d_in[wb + 2];
        const float* kb = (const float*)d_in[wb + 3];
        const float* vw = (const float*)d_in[wb + 4];
        const float* vb = (const float*)d_in[wb + 5];
        const float* ow = (const float*)d_in[wb + 6];
        const float* ob = (const float*)d_in[wb + 7];

        float* outp = (float*)d_out + out_off;

        proj_kernel<<<B * (N / TN), 192>>>(f1, f2, qw, qb, kw, kb, vw, vb, C, N, H);

        dim3 sg(N / 64, N / 64, B * NH);
        scores_kernel<<<sg, dim3(16, 16)>>>(N);

        attn_kernel<<<B * NH * N, 256, (size_t)N * sizeof(unsigned int)>>>(N);

        oproj_kernel<<<B * (N / TN), 192>>>(ow, ob, outp, N);

        out_off += (size_t)B * TD * N;
    }
}

// round 3
// speedup vs baseline: 1.9872x; 1.4390x over previous
#include <cuda_runtime.h>
#include <cuda_bf16.h>
#include <cstdint>

// ---------------------------------------------------------------------------
// GlobalMatchingTokenizer: 3 levels of efficient global matching attention.
// B=2, C={64,128,192}, H=W={64,32,16}, N=H*W, TOKEN_DIM=192, NUM_HEADS=4,
// HEAD_DIM=48, TOPK=128.
// ---------------------------------------------------------------------------

#define NH 4
#define HD 48
#define TD 192
#define KSEL 128
#define TN 16      // query-position tile for proj/oproj
#define CAP 256    // candidate cap for radix select refinement
#define SPAD 52    // smem row pad for scores tiles

// Scratch (device globals: allowed; no dynamic allocation anywhere).
__device__ float g_S[134217728];            // 2*4*4096*4096 floats = 512 MB
__device__ float g_Q[2 * NH * 4096 * HD];
__device__ float g_K[2 * NH * 4096 * HD];
__device__ float g_V[2 * NH * 4096 * HD];
__device__ float g_O[2 * NH * 4096 * HD];

// ---------------------------------------------------------------------------
// Kernel 1: QKV projection + positional encoding, n-tiled for weight reuse.
// grid = B*(N/TN), 384 threads: channel = tid%192, position-half = tid/192.
// ---------------------------------------------------------------------------
__global__ void proj_kernel(const float* __restrict__ f1,
                            const float* __restrict__ f2,
                            const float* __restrict__ qw, const float* __restrict__ qb,
                            const float* __restrict__ kw, const float* __restrict__ kb,
                            const float* __restrict__ vw, const float* __restrict__ vb,
                            int C, int N, int W)
{
    __shared__ float s1[TD][TN];
    __shared__ float s2[TD][TN];
    const int tid  = threadIdx.x;               // 0..383
    const int t    = tid % TD;                  // output channel
    const int half = tid / TD;                  // 0/1
    const int nt = N / TN;
    const int n0 = (blockIdx.x % nt) * TN;
    const int b  = blockIdx.x / nt;

    for (int i = tid; i < C * TN; i += 384) {
        const int c = i / TN, j = i % TN;
        s1[c][j] = f1[((size_t)b * C + c) * N + n0 + j];
        s2[c][j] = f2[((size_t)b * C + c) * N + n0 + j];
    }
    __syncthreads();

    const int j0 = half * (TN / 2);
    float aq[TN / 2], ak[TN / 2], av[TN / 2];
    const float bq = qb[t], bk = kb[t], bv = vb[t];
    #pragma unroll
    for (int j = 0; j < TN / 2; ++j) { aq[j] = bq; ak[j] = bk; av[j] = bv; }

    for (int c = 0; c < C; ++c) {
        const float wq = qw[c * TD + t];
        const float wk = kw[c * TD + t];
        const float wv = vw[c * TD + t];
        #pragma unroll
        for (int j = 0; j < TN / 2; ++j) {
            const float a1 = s1[c][j0 + j];
            const float a2 = s2[c][j0 + j];
            aq[j] = fmaf(a1, wq, aq[j]);
            ak[j] = fmaf(a2, wk, ak[j]);
            av[j] = fmaf(a2, wv, av[j]);
        }
    }

    // 2D sinusoidal positional encoding.
    const float step = -9.210340371976184f / 96.0f;  // -ln(10000)/96
    const float div  = expf(step * (float)(t < 96 ? t : t - 96));
    #pragma unroll
    for (int j = 0; j < TN / 2; ++j) {
        const int n = n0 + j0 + j;
        const float pe = (t < 96) ? sinf((float)(n % W) * div)
                                  : cosf((float)(n / W) * div);
        aq[j] += pe;
        ak[j] += pe;
    }

    const int h = t / HD;
    const int d = t % HD;
    const size_t base = (((size_t)b * NH + h) * N + n0 + j0) * HD + d;
    #pragma unroll
    for (int j = 0; j < TN / 2; ++j) {
        g_Q[base + (size_t)j * HD] = aq[j];
        g_K[base + (size_t)j * HD] = ak[j];
        g_V[base + (size_t)j * HD] = av[j];
    }
}

// ---------------------------------------------------------------------------
// Kernel 2: scores GEMM. S[bh][n][m] = scale * dot(Q[bh][n], K[bh][m]).
// grid = (N/128, N/128, B*NH), 256 threads, 8x8 per thread, interleaved
// row/col assignment (stride 16) for conflict-free smem reads.
// ---------------------------------------------------------------------------
__global__ void __launch_bounds__(256) scores_kernel(int N)
{
    __shared__ float Qs[128][SPAD];
    __shared__ float Ks[128][SPAD];

    const int bh = blockIdx.z;
    const float* __restrict__ Qb = g_Q + (size_t)bh * N * HD;
    const float* __restrict__ Kb = g_K + (size_t)bh * N * HD;
    float* __restrict__ Sb = g_S + (size_t)bh * N * N;

    const int tid = threadIdx.x;
    const int rb = blockIdx.y * 128;
    const int cb = blockIdx.x * 128;

    for (int i = tid; i < 128 * 12; i += 256) {
        const int r = i / 12, q = (i % 12) * 4;
        *(float4*)&Qs[r][q] = *(const float4*)(Qb + (size_t)(rb + r) * HD + q);
        *(float4*)&Ks[r][q] = *(const float4*)(Kb + (size_t)(cb + r) * HD + q);
    }
    __syncthreads();

    const int ty = tid >> 4, tx = tid & 15;
    float acc[8][8] = {};

    #pragma unroll
    for (int kk = 0; kk < HD; kk += 2) {
        float2 qv[8], kv[8];
        #pragma unroll
        for (int i = 0; i < 8; ++i) {
            qv[i] = *(const float2*)&Qs[ty + 16 * i][kk];
            kv[i] = *(const float2*)&Ks[tx + 16 * i][kk];
        }
        #pragma unroll
        for (int i = 0; i < 8; ++i)
            #pragma unroll
            for (int j = 0; j < 8; ++j) {
                acc[i][j] = fmaf(qv[i].x, kv[j].x, acc[i][j]);
                acc[i][j] = fmaf(qv[i].y, kv[j].y, acc[i][j]);
            }
    }

    const float scale = 0.14433756729740643f;  // 1/sqrt(48)
    #pragma unroll
    for (int i = 0; i < 8; ++i) {
        const size_t ro = (size_t)(rb + ty + 16 * i) * N + cb + tx;
        #pragma unroll
        for (int j = 0; j < 8; ++j)
            Sb[ro + 16 * j] = acc[i][j] * scale;
    }
}

// ---------------------------------------------------------------------------
// Kernel 3: per query row: exact top-128 via radix select (parallel bucket
// pick), softmax, weighted V sum. grid = B*NH*N rows, 256 threads.
// ---------------------------------------------------------------------------
__device__ __forceinline__ unsigned int floatToKey(float f)
{
    unsigned int u = __float_as_uint(f);
    return (u & 0x80000000u) ? ~u : (u | 0x80000000u);
}
__device__ __forceinline__ float keyToFloat(unsigned int u)
{
    unsigned int b = (u & 0x80000000u) ? (u & 0x7fffffffu) : ~u;
    return __uint_as_float(b);
}

__global__ void attn_kernel(int N)
{
    extern __shared__ unsigned int keys[];      // N sortable keys
    __shared__ unsigned int hist[256];
    __shared__ unsigned int ckey[CAP];
    __shared__ int          cidx[CAP];
    __shared__ float        wl[KSEL];
    __shared__ int          ml[KSEL];
    __shared__ float        accs[HD];
    __shared__ int          wsum[8];
    __shared__ int          wsuf[9];
    __shared__ unsigned int s_prefix, s_maxkey;
    __shared__ int          s_need, s_cand, s_cnt, s_ccnt;
    __shared__ float        s_Z;

    const int tid = threadIdx.x;                // 0..255
    const size_t row = blockIdx.x;              // (b*NH+h)*N + n
    const float* __restrict__ Srow = g_S + row * (size_t)N;

    if (tid == 0) {
        s_maxkey = 0u; s_cnt = 0; s_ccnt = 0; s_Z = 0.f;
        s_prefix = 0u; s_need = KSEL;
    }
    if (tid < HD) accs[tid] = 0.f;
    hist[tid] = 0u;
    __syncthreads();

    // Fused load + key conversion + pass-0 histogram (top 8 bits).
    unsigned int lmax = 0u;
    for (int m = tid; m < N; m += 256) {
        const unsigned int u = floatToKey(Srow[m]);
        keys[m] = u;
        lmax = max(lmax, u);
        atomicAdd(&hist[u >> 24], 1u);
    }
    #pragma unroll
    for (int off = 16; off; off >>= 1)
        lmax = max(lmax, __shfl_down_sync(0xffffffffu, lmax, off));
    if ((tid & 31) == 0) atomicMax(&s_maxkey, lmax);
    __syncthreads();

    // Radix select: parallel suffix-scan bucket pick; refine bytes as needed.
    int p = 0;
    for (;;) {
        const int need = s_need;
        const int h = (int)hist[tid];
        int x = h;
        #pragma unroll
        for (int off = 1; off < 32; off <<= 1) {
            const int y = __shfl_down_sync(0xffffffffu, x, off);
            if ((tid & 31) + off < 32) x += y;
        }
        if ((tid & 31) == 0) wsum[tid >> 5] = x;
        __syncthreads();
        if (tid == 0) {
            int s = 0;
            for (int w = 7; w >= 0; --w) { s += wsum[w]; wsuf[w] = s; }
            wsuf[8] = 0;
        }
        __syncthreads();
        const int suffix  = x + wsuf[(tid >> 5) + 1];
        const int sufNext = suffix - h;
        if (suffix >= need && sufNext < need) {
            s_need   = need - sufNext;
            s_cand   = h;
            s_prefix = (s_prefix << 8) | (unsigned int)tid;
        }
        __syncthreads();
        if (s_cand <= CAP || p == 3) break;

        hist[tid] = 0u;
        __syncthreads();
        const unsigned int pfx = s_prefix;
        const int shift = 24 - 8 * p, nshift = shift - 8;
        for (int m = tid; m < N; m += 256) {
            const unsigned int u = keys[m];
            if ((u >> shift) == pfx)
                atomicAdd(&hist[(u >> nshift) & 255u], 1u);
        }
        __syncthreads();
        ++p;
    }

    const int shift = 24 - 8 * p;
    const unsigned int P = s_prefix;
    const int needC = s_need;
    const bool capok = (s_cand <= CAP);
    const float smax = keyToFloat(s_maxkey);

    // Fused: definite winners (> bucket) + candidate gather (== bucket).
    for (int m = tid; m < N; m += 256) {
        const unsigned int u = keys[m];
        const unsigned int ub = u >> shift;
        if (ub > P) {
            const int slot = atomicAdd(&s_cnt, 1);
            if (slot < KSEL) {
                wl[slot] = __expf(keyToFloat(u) - smax);
                ml[slot] = m;
            }
        } else if (ub == P && capok) {
            const int slot = atomicAdd(&s_ccnt, 1);
            if (slot < CAP) { ckey[slot] = u; cidx[slot] = m; }
        }
    }
    __syncthreads();

    if (capok) {
        // Exact rank among bucket candidates (key desc, index asc).
        const int c = min(s_ccnt, CAP);
        for (int i = tid; i < c; i += 256) {
            const unsigned int ki = ckey[i];
            const int idi = cidx[i];
            int r = 0;
            for (int j = 0; j < c; ++j) {
                const unsigned int kj = ckey[j];
                r += (kj > ki) || (kj == ki && cidx[j] < idi);
            }
            if (r < needC) {
                const int slot = atomicAdd(&s_cnt, 1);
                if (slot < KSEL) {
                    wl[slot] = __expf(keyToFloat(ki) - smax);
                    ml[slot] = idi;
                }
            }
        }
    } else {
        // Pathological: >CAP identical 32-bit keys (p==3, shift==0).
        for (int m = tid; m < N; m += 256) {
            const unsigned int u = keys[m];
            if (u == P) {
                int r = 0;
                for (int j = 0; j < m; ++j) r += (keys[j] == P);
                if (r < needC) {
                    const int slot = atomicAdd(&s_cnt, 1);
                    if (slot < KSEL) {
                        wl[slot] = __expf(keyToFloat(u) - smax);
                        ml[slot] = m;
                    }
                }
            }
        }
    }
    __syncthreads();

    const int total = min(s_cnt, KSEL);

    // Z = sum of selected weights (shuffle reduce, few atomics).
    float z = (tid < total) ? wl[tid] : 0.f;
    #pragma unroll
    for (int off = 16; off; off >>= 1)
        z += __shfl_down_sync(0xffffffffu, z, off);
    if ((tid & 31) == 0) atomicAdd(&s_Z, z);
    __syncthreads();

    const size_t bh = row / (size_t)N;
    const float* __restrict__ Vb = g_V + bh * (size_t)N * HD;

    if (tid < 192) {
        const int d = tid % HD;
        const int ch = tid / HD;   // 4 chunks over selected indices
        float a = 0.f;
        #pragma unroll 4
        for (int i = ch; i < total; i += 4)
            a = fmaf(wl[i], __ldg(&Vb[(size_t)ml[i] * HD + d]), a);
        atomicAdd(&accs[d], a);
    }
    __syncthreads();

    if (tid < HD)
        g_O[row * HD + tid] = accs[tid] / s_Z;
}

// ---------------------------------------------------------------------------
// Kernel 4: output projection, n-tiled, 384 threads (2 position halves).
// ---------------------------------------------------------------------------
__global__ void oproj_kernel(const float* __restrict__ ow,
                             const float* __restrict__ ob,
                             float* __restrict__ out, int N)
{
    __shared__ float o[TD][TN + 1];
    const int tid  = threadIdx.x;               // 0..383
    const int t    = tid % TD;
    const int half = tid / TD;
    const int nt = N / TN;
    const int n0 = (blockIdx.x % nt) * TN;
    const int b  = blockIdx.x / nt;

    for (int i = tid; i < TD * TN; i += 384) {
        const int j  = i / TD;
        const int td = i % TD;
        const int h = td / HD, d = td % HD;
        o[td][j] = g_O[(((size_t)b * NH + h) * N + n0 + j) * HD + d];
    }
    __syncthreads();

    const int j0 = half * (TN / 2);
    float acc[TN / 2];
    const float bias = ob[t];
    #pragma unroll
    for (int j = 0; j < TN / 2; ++j) acc[j] = bias;

    for (int j = 0; j < TD; ++j) {
        const float w = ow[j * TD + t];
        #pragma unroll
        for (int jj = 0; jj < TN / 2; ++jj)
            acc[jj] = fmaf(o[j][j0 + jj], w, acc[jj]);
    }

    float4* op = (float4*)(out + ((size_t)b * TD + t) * N + n0 + j0);
    #pragma unroll
    for (int q = 0; q < TN / 8; ++q)
        op[q] = make_float4(acc[4 * q], acc[4 * q + 1], acc[4 * q + 2], acc[4 * q + 3]);
}

// ---------------------------------------------------------------------------
// Launch: 3 levels sequentially.
// ---------------------------------------------------------------------------
extern "C" void kernel_launch(void* const* d_in, const int* in_sizes, int n_in,
                              void* d_out, int out_size)
{
    (void)in_sizes; (void)n_in; (void)out_size;

    const int Cs[3] = {64, 128, 192};
    const int Hs[3] = {64, 32, 16};

    size_t out_off = 0;
    for (int l = 0; l < 3; ++l) {
        const int C = Cs[l];
        const int H = Hs[l];
        const int N = H * H;
        const int B = 2;

        const float* f1 = (const float*)d_in[2 * l + 0];
        const float* f2 = (const float*)d_in[2 * l + 1];
        const int wb = 6 + 8 * l;
        const float* qw = (const float*)d_in[wb + 0];
        const float* qb = (const float*)d_in[wb + 1];
        const float* kw = (const float*)d_in[wb + 2];
        const float* kb = (const float*)d_in[wb + 3];
        const float* vw = (const float*)d_in[wb + 4];
        const float* vb = (const float*)d_in[wb + 5];
        const float* ow = (const float*)d_in[wb + 6];
        const float* ob = (const float*)d_in[wb + 7];

        float* outp = (float*)d_out + out_off;

        proj_kernel<<<B * (N / TN), 384>>>(f1, f2, qw, qb, kw, kb, vw, vb, C, N, H);

        dim3 sg(N / 128, N / 128, B * NH);
        scores_kernel<<<sg, 256>>>(N);

        attn_kernel<<<B * NH * N, 256, (size_t)N * sizeof(unsigned int)>>>(N);

        oproj_kernel<<<B * (N / TN), 384>>>(ow, ob, outp, N);

        out_off += (size_t)B * TD * N;
    }
}